// round 15
// baseline (speedup 1.0000x reference)
#include <cuda_runtime.h>
#include <cuda_fp16.h>
#include <cstdint>

#define S_TOK 4096
#define DIM   2048
#define NE    8
#define FF    5504
#define CAP   1024

typedef __half fp16;

// ---------------- device-global scratch ------------------------------------
__device__ float g_logits[S_TOK * NE];
__device__ int   g_idx1[S_TOK], g_idx2[S_TOK];
__device__ float g_g1[S_TOK], g_g2[S_TOK];
__device__ int   g_slot1[S_TOK], g_slot2[S_TOK];
__device__ int   g_tok4slot[NE * CAP];
__device__ float g_wslot[NE * CAP];
__device__ int   g_count1[NE];
__device__ float g_me[NE];
__device__ float g_laux;

__device__ fp16  g_ah[(size_t)NE * CAP * DIM];
__device__ fp16  g_w1h[(size_t)NE * DIM * FF];
__device__ fp16  g_w3h[(size_t)NE * DIM * FF];
__device__ fp16  g_w2h[(size_t)NE * FF * DIM];
__device__ fp16  g_hh[(size_t)NE * CAP * FF];

// ---------------- helpers ----------------------------------------------------
__device__ __forceinline__ uint32_t smem_to_u32(const void* p) {
    uint32_t a;
    asm("{ .reg .u64 t; cvta.to.shared.u64 t, %1; cvt.u32.u64 %0, t; }"
        : "=r"(a) : "l"(p));
    return a;
}
__device__ __forceinline__ void cpasync16(uint32_t dst, const void* src) {
    asm volatile("cp.async.cg.shared.global [%0], [%1], 16;" :: "r"(dst), "l"(src));
}
#define CP_COMMIT() asm volatile("cp.async.commit_group;" ::: "memory")
#define CP_WAIT1()  asm volatile("cp.async.wait_group 1;" ::: "memory")
#define CP_WAIT0()  asm volatile("cp.async.wait_group 0;" ::: "memory")

__device__ __forceinline__ void ldsm_x4(uint32_t& r0, uint32_t& r1, uint32_t& r2,
                                        uint32_t& r3, uint32_t a) {
    asm volatile("ldmatrix.sync.aligned.m8n8.x4.shared.b16 {%0,%1,%2,%3}, [%4];"
                 : "=r"(r0), "=r"(r1), "=r"(r2), "=r"(r3) : "r"(a));
}
__device__ __forceinline__ void ldsm_x4t(uint32_t& r0, uint32_t& r1, uint32_t& r2,
                                         uint32_t& r3, uint32_t a) {
    asm volatile("ldmatrix.sync.aligned.m8n8.x4.trans.shared.b16 {%0,%1,%2,%3}, [%4];"
                 : "=r"(r0), "=r"(r1), "=r"(r2), "=r"(r3) : "r"(a));
}
__device__ __forceinline__ void mma16816(float* c, const uint32_t* a,
                                         uint32_t b0, uint32_t b1) {
    asm volatile("mma.sync.aligned.m16n8k16.row.col.f32.f16.f16.f32 "
                 "{%0,%1,%2,%3},{%4,%5,%6,%7},{%8,%9},{%0,%1,%2,%3};"
                 : "+f"(c[0]), "+f"(c[1]), "+f"(c[2]), "+f"(c[3])
                 : "r"(a[0]), "r"(a[1]), "r"(a[2]), "r"(a[3]), "r"(b0), "r"(b1));
}
__device__ __forceinline__ uint32_t pkh(fp16 a, fp16 b) {
    return (uint32_t)__half_as_ushort(a) | ((uint32_t)__half_as_ushort(b) << 16);
}

// ---------------- prep: reset small scratch only -----------------------------
__global__ void k_prep() {
    int i = blockIdx.x * blockDim.x + threadIdx.x;
    if (i < NE * CAP) g_tok4slot[i] = -1;
    if (i < NE) g_me[i] = 0.f;
}

// ---------------- gating ------------------------------------------------------
__global__ void k_logits(const float* __restrict__ x, const float* __restrict__ wg) {
    int s = blockIdx.x;
    float acc[NE];
#pragma unroll
    for (int e = 0; e < NE; e++) acc[e] = 0.f;
    const float* xr = x + (size_t)s * DIM;
    for (int j = threadIdx.x; j < DIM; j += blockDim.x) {
        float xv = xr[j];
        float4 w0 = *(const float4*)(wg + (size_t)j * NE);
        float4 w1v = *(const float4*)(wg + (size_t)j * NE + 4);
        acc[0] += xv * w0.x;  acc[1] += xv * w0.y;
        acc[2] += xv * w0.z;  acc[3] += xv * w0.w;
        acc[4] += xv * w1v.x; acc[5] += xv * w1v.y;
        acc[6] += xv * w1v.z; acc[7] += xv * w1v.w;
    }
#pragma unroll
    for (int off = 16; off; off >>= 1)
#pragma unroll
        for (int e = 0; e < NE; e++)
            acc[e] += __shfl_down_sync(0xffffffffu, acc[e], off);
    __shared__ float red[4][NE];
    int lane = threadIdx.x & 31, wp = threadIdx.x >> 5;
    if (lane == 0)
#pragma unroll
        for (int e = 0; e < NE; e++) red[wp][e] = acc[e];
    __syncthreads();
    if (threadIdx.x < NE)
        g_logits[(size_t)s * NE + threadIdx.x] =
            red[0][threadIdx.x] + red[1][threadIdx.x] +
            red[2][threadIdx.x] + red[3][threadIdx.x];
}
__global__ void k_top2() {
    __shared__ float sme[NE];
    if (threadIdx.x < NE) sme[threadIdx.x] = 0.f;
    __syncthreads();
    int s = blockIdx.x * blockDim.x + threadIdx.x;
    float l[NE];
    float4 a = *(const float4*)(g_logits + (size_t)s * NE);
    float4 b = *(const float4*)(g_logits + (size_t)s * NE + 4);
    l[0]=a.x; l[1]=a.y; l[2]=a.z; l[3]=a.w; l[4]=b.x; l[5]=b.y; l[6]=b.z; l[7]=b.w;
    float mx = l[0];
#pragma unroll
    for (int e = 1; e < NE; e++) mx = fmaxf(mx, l[e]);
    float g[NE], sum = 0.f;
#pragma unroll
    for (int e = 0; e < NE; e++) { g[e] = __expf(l[e] - mx); sum += g[e]; }
    float inv = 1.f / sum;
    int i1 = 0; float b1 = l[0];
#pragma unroll
    for (int e = 1; e < NE; e++) if (l[e] > b1) { b1 = l[e]; i1 = e; }
    int i2 = 0; float b2 = -3.0e38f;
#pragma unroll
    for (int e = 0; e < NE; e++) if (e != i1 && l[e] > b2) { b2 = l[e]; i2 = e; }
    g_idx1[s] = i1; g_idx2[s] = i2;
    g_g1[s] = g[i1] * inv; g_g2[s] = g[i2] * inv;
#pragma unroll
    for (int e = 0; e < NE; e++) atomicAdd(&sme[e], g[e] * inv);
    __syncthreads();
    if (threadIdx.x < NE) atomicAdd(&g_me[threadIdx.x], sme[threadIdx.x]);
}
// scan + per-slot gate weights + aux outputs (single block)
__global__ void k_scan(float* __restrict__ out, int out_size) {
    __shared__ int si1[S_TOK], si2[S_TOK];
    int tid = threadIdx.x;
    for (int i = tid; i < S_TOK; i += blockDim.x) { si1[i] = g_idx1[i]; si2[i] = g_idx2[i]; }
    __syncthreads();
    int lane = tid & 31, e = tid >> 5;
    unsigned lm = (1u << lane) - 1u;
    if (e < NE) {
        int c1 = 0;
        for (int s0 = 0; s0 < S_TOK; s0 += 32) {
            int s = s0 + lane;
            int m = (si1[s] == e);
            unsigned bal = __ballot_sync(0xffffffffu, m);
            if (m) {
                int pos = c1 + __popc(bal & lm);
                if (pos < CAP) { g_slot1[s] = pos; g_tok4slot[e * CAP + pos] = s; }
                else g_slot1[s] = -1;
            }
            c1 += __popc(bal);
        }
        if (lane == 0) g_count1[e] = c1;
        int c2 = c1;
        for (int s0 = 0; s0 < S_TOK; s0 += 32) {
            int s = s0 + lane;
            int m = (si2[s] == e);
            unsigned bal = __ballot_sync(0xffffffffu, m);
            if (m) {
                int pos = c2 + __popc(bal & lm);
                if (pos < CAP) { g_slot2[s] = pos; g_tok4slot[e * CAP + pos] = s; }
                else g_slot2[s] = -1;
            }
            c2 += __popc(bal);
        }
    }
    __syncthreads();
    for (int s = tid; s < S_TOK; s += blockDim.x) {
        int sl1 = g_slot1[s], sl2 = g_slot2[s];
        float g1 = (sl1 >= 0) ? g_g1[s] : 0.f;
        float g2 = (sl2 >= 0) ? g_g2[s] : 0.f;
        float dn = fmaxf(g1 + g2, 1e-9f);
        if (sl1 >= 0) g_wslot[g_idx1[s] * CAP + sl1] = g1 / dn;
        if (sl2 >= 0) g_wslot[g_idx2[s] * CAP + sl2] = g2 / dn;
    }
    if (tid == 0) {
        float acc = 0.f;
        for (int i = 0; i < NE; i++)
            acc += (g_me[i] / (float)S_TOK) * ((float)g_count1[i] / (float)S_TOK);
        g_laux = acc * (float)NE;
        size_t base = (size_t)S_TOK * DIM;
        if ((size_t)out_size > base) out[base] = g_laux;
    }
    if (tid >= 1 && tid <= NE) {
        size_t base = (size_t)S_TOK * DIM;
        if ((size_t)out_size >= base + 1 + NE)
            out[base + tid] = (float)g_count1[tid - 1];
    }
}

// ---------------- dispatch: gather token rows -> A fp16 ---------------------
__global__ void k_dispatch_h(const float* __restrict__ x) {
    int slot = blockIdx.x;
    int s = g_tok4slot[slot];
    uint2* ah = (uint2*)(g_ah + (size_t)slot * DIM);
    if (s >= 0) {
        const float4* xr = (const float4*)(x + (size_t)s * DIM);
        for (int j = threadIdx.x; j < DIM / 4; j += blockDim.x) {
            float4 v = xr[j];
            ah[j] = make_uint2(pkh(__float2half_rn(v.x), __float2half_rn(v.y)),
                               pkh(__float2half_rn(v.z), __float2half_rn(v.w)));
        }
    } else {
        uint2 z = make_uint2(0u, 0u);
        for (int j = threadIdx.x; j < DIM / 4; j += blockDim.x) ah[j] = z;
    }
}

// ---------------- weight convert: fp32 -> fp16 ------------------------------
__global__ void k_wcvt(const float4* __restrict__ src, uint2* __restrict__ hh, size_t n4) {
    size_t i = (size_t)blockIdx.x * blockDim.x + threadIdx.x;
    if (i >= n4) return;
    float4 v = src[i];
    hh[i] = make_uint2(pkh(__float2half_rn(v.x), __float2half_rn(v.y)),
                       pkh(__float2half_rn(v.z), __float2half_rn(v.w)));
}
// fused dual-source conversion (w1 + w3 in one launch)
__global__ void k_wcvt2(const float4* __restrict__ s1, uint2* __restrict__ d1,
                        const float4* __restrict__ s2, uint2* __restrict__ d2,
                        size_t n4) {
    size_t i = (size_t)blockIdx.x * blockDim.x + threadIdx.x;
    if (i >= n4) return;
    float4 a = s1[i];
    d1[i] = make_uint2(pkh(__float2half_rn(a.x), __float2half_rn(a.y)),
                       pkh(__float2half_rn(a.z), __float2half_rn(a.w)));
    float4 b = s2[i];
    d2[i] = make_uint2(pkh(__float2half_rn(b.x), __float2half_rn(b.y)),
                       pkh(__float2half_rn(b.z), __float2half_rn(b.w)));
}

// ---------------- tiling constants (BK=64) ----------------------------------
#define ASTR64  144u
#define A_SZ64  (128u * ASTR64)           // 18432
#define BSTRN   272u
#define BSTRH   144u
#define NSTAGE  3

// ---------------- dual-B SwiGLU GEMM: 256 thr, BM=128 BN=64 BK=64 -----------
#define D_BSZ   (64u * BSTRH)
#define D_STG   (A_SZ64 + 2u * D_BSZ)
#define D_GSMEM (NSTAGE * D_STG)

__global__ void __launch_bounds__(256, 2)
k_gemm_dual(const fp16* __restrict__ Ag, const fp16* __restrict__ B1g,
            const fp16* __restrict__ B3g, fp16* __restrict__ Hg,
            int N, int K) {
    extern __shared__ __align__(16) uint8_t smem[];
    const int M = CAP;
    int tid = threadIdx.x, lane = tid & 31, wid = tid >> 5;
    int wm = wid & 1, wn = wid >> 1;
    int n0 = blockIdx.x * 64, m0 = blockIdx.y * 128, e = blockIdx.z;
    const fp16* A0 = Ag + (size_t)e * M * K;
    const fp16* B1 = B1g + (size_t)e * K * N;
    const fp16* B3 = B3g + (size_t)e * K * N;
    const int NIT = K / 64;
    uint32_t sb = smem_to_u32(smem);

    float acc1[4][2][4], acc3[4][2][4];
#pragma unroll
    for (int a = 0; a < 4; a++)
#pragma unroll
        for (int b = 0; b < 2; b++)
#pragma unroll
            for (int c = 0; c < 4; c++) { acc1[a][b][c] = 0.f; acc3[a][b][c] = 0.f; }

    auto load_stage = [&](int kc, int slot) {
        uint32_t st = sb + (uint32_t)slot * D_STG;
#pragma unroll
        for (int j = 0; j < 4; j++) {
            int id = tid + j * 256;
            int row = id >> 3, c = id & 7;
            cpasync16(st + (uint32_t)row * ASTR64 + c * 16,
                      A0 + (size_t)(m0 + row) * K + kc * 64 + c * 8);
        }
#pragma unroll
        for (int j = 0; j < 2; j++) {
            int id = tid + j * 256;
            int k = id >> 3, c = id & 7;
            const size_t gb = (size_t)(kc * 64 + k) * N + n0 + c * 8;
            cpasync16(st + A_SZ64 + (uint32_t)k * BSTRH + c * 16, B1 + gb);
            cpasync16(st + A_SZ64 + D_BSZ + (uint32_t)k * BSTRH + c * 16, B3 + gb);
        }
    };

    int mm = lane >> 3;
    int rowin = (mm & 1) * 8 + (lane & 7);
    int c0 = mm >> 1;
    uint32_t aOff = (uint32_t)(wm * 64 + rowin) * ASTR64 + (uint32_t)c0 * 16;
    int p = lane >> 4, mrow = (lane >> 3) & 1;
    int kin = mrow * 8 + (lane & 7);
    uint32_t bOff = (uint32_t)kin * BSTRH + (uint32_t)(wn * 2 + p) * 16;

    load_stage(0, 0); CP_COMMIT();
    load_stage(1, 1); CP_COMMIT();
    for (int i = 0; i < NIT; i++) {
        if (i + 1 < NIT) CP_WAIT1(); else CP_WAIT0();
        __syncthreads();
        uint32_t st = sb + (uint32_t)(i % NSTAGE) * D_STG;
#pragma unroll
        for (int s = 0; s < 4; s++) {
            uint32_t a[4][4], b1r[4], b3r[4];
#pragma unroll
            for (int mt = 0; mt < 4; mt++)
                ldsm_x4(a[mt][0], a[mt][1], a[mt][2], a[mt][3],
                        st + aOff + (uint32_t)mt * (16u * ASTR64) + (uint32_t)s * 32);
            ldsm_x4t(b1r[0], b1r[1], b1r[2], b1r[3],
                     st + A_SZ64 + bOff + (uint32_t)s * (16u * BSTRH));
            ldsm_x4t(b3r[0], b3r[1], b3r[2], b3r[3],
                     st + A_SZ64 + D_BSZ + bOff + (uint32_t)s * (16u * BSTRH));
#pragma unroll
            for (int mt = 0; mt < 4; mt++)
#pragma unroll
                for (int nt = 0; nt < 2; nt++) {
                    mma16816(acc1[mt][nt], a[mt], b1r[nt * 2], b1r[nt * 2 + 1]);
                    mma16816(acc3[mt][nt], a[mt], b3r[nt * 2], b3r[nt * 2 + 1]);
                }
        }
        if (i + 2 < NIT) load_stage(i + 2, (i + 2) % NSTAGE);
        CP_COMMIT();
    }

    int rg = lane >> 2, cgi = (lane & 3) * 2;
    size_t ebase = (size_t)e * M * N;
#pragma unroll
    for (int mt = 0; mt < 4; mt++)
#pragma unroll
        for (int nt = 0; nt < 2; nt++) {
            int row = m0 + wm * 64 + mt * 16 + rg;
            int col = n0 + wn * 16 + nt * 8 + cgi;
            size_t o0 = ebase + (size_t)row * N + col;
            size_t o1 = ebase + (size_t)(row + 8) * N + col;
            float t0 = acc1[mt][nt][0], t1 = acc1[mt][nt][1];
            float t2 = acc1[mt][nt][2], t3 = acc1[mt][nt][3];
            float h0 = t0 / (1.f + __expf(-t0)) * acc3[mt][nt][0];
            float h1 = t1 / (1.f + __expf(-t1)) * acc3[mt][nt][1];
            float h2 = t2 / (1.f + __expf(-t2)) * acc3[mt][nt][2];
            float h3 = t3 / (1.f + __expf(-t3)) * acc3[mt][nt][3];
            *(uint32_t*)(Hg + o0) = pkh(__float2half_rn(h0), __float2half_rn(h1));
            *(uint32_t*)(Hg + o1) = pkh(__float2half_rn(h2), __float2half_rn(h3));
        }
}

// ---------------- single-B GEMM + fused combine epilogue (R12 proven) -------
#define S_BSZ   (64u * BSTRN)
#define S_STG   (A_SZ64 + S_BSZ)
#define S_GSMEM (NSTAGE * S_STG)

__global__ void __launch_bounds__(256, 2)
k_gemm_s(const fp16* __restrict__ Ag, const fp16* __restrict__ Bg,
         float* __restrict__ out, int N, int K) {
    extern __shared__ __align__(16) uint8_t smem[];
    const int M = CAP;
    int tid = threadIdx.x, lane = tid & 31, wid = tid >> 5;
    int wm = wid & 1, wn = wid >> 1;
    int n0 = blockIdx.x * 128, m0 = blockIdx.y * 128, e = blockIdx.z;
    const fp16* A0 = Ag + (size_t)e * M * K;
    const fp16* B0 = Bg + (size_t)e * K * N;
    const int NIT = K / 64;
    uint32_t sb = smem_to_u32(smem);

    float acc[4][4][4];
#pragma unroll
    for (int a = 0; a < 4; a++)
#pragma unroll
        for (int b = 0; b < 4; b++)
#pragma unroll
            for (int c = 0; c < 4; c++) acc[a][b][c] = 0.f;

    auto load_stage = [&](int kc, int slot) {
        uint32_t st = sb + (uint32_t)slot * S_STG;
#pragma unroll
        for (int j = 0; j < 4; j++) {
            int id = tid + j * 256;
            int row = id >> 3, c = id & 7;
            cpasync16(st + (uint32_t)row * ASTR64 + c * 16,
                      A0 + (size_t)(m0 + row) * K + kc * 64 + c * 8);
        }
#pragma unroll
        for (int j = 0; j < 4; j++) {
            int id = tid + j * 256;
            int k = id >> 4, c = id & 15;
            cpasync16(st + A_SZ64 + (uint32_t)k * BSTRN + c * 16,
                      B0 + (size_t)(kc * 64 + k) * N + n0 + c * 8);
        }
    };

    int mm = lane >> 3;
    int rowin = (mm & 1) * 8 + (lane & 7);
    int c0 = mm >> 1;
    uint32_t aOff = (uint32_t)(wm * 64 + rowin) * ASTR64 + (uint32_t)c0 * 16;
    int p = lane >> 4, mrow = (lane >> 3) & 1;
    int kin = mrow * 8 + (lane & 7);
    uint32_t bOff = (uint32_t)kin * BSTRN + (uint32_t)(wn * 4 + p) * 16;

    load_stage(0, 0); CP_COMMIT();
    load_stage(1, 1); CP_COMMIT();
    for (int i = 0; i < NIT; i++) {
        if (i + 1 < NIT) CP_WAIT1(); else CP_WAIT0();
        __syncthreads();
        uint32_t st = sb + (uint32_t)(i % NSTAGE) * S_STG;
#pragma unroll
        for (int s = 0; s < 4; s++) {
            uint32_t a[4][4], bh[2][4];
#pragma unroll
            for (int mt = 0; mt < 4; mt++)
                ldsm_x4(a[mt][0], a[mt][1], a[mt][2], a[mt][3],
                        st + aOff + (uint32_t)mt * (16u * ASTR64) + (uint32_t)s * 32);
            ldsm_x4t(bh[0][0], bh[0][1], bh[0][2], bh[0][3],
                     st + A_SZ64 + bOff + (uint32_t)s * (16u * BSTRN));
            ldsm_x4t(bh[1][0], bh[1][1], bh[1][2], bh[1][3],
                     st + A_SZ64 + bOff + (uint32_t)s * (16u * BSTRN) + 32u);
#pragma unroll
            for (int mt = 0; mt < 4; mt++)
#pragma unroll
                for (int nt = 0; nt < 4; nt++)
                    mma16816(acc[mt][nt], a[mt], bh[nt >> 1][(nt & 1) * 2],
                             bh[nt >> 1][(nt & 1) * 2 + 1]);
        }
        if (i + 2 < NIT) load_stage(i + 2, (i + 2) % NSTAGE);
        CP_COMMIT();
    }

    int rg = lane >> 2, cgi = (lane & 3) * 2;
#pragma unroll
    for (int mt = 0; mt < 4; mt++) {
        int r0 = m0 + wm * 64 + mt * 16 + rg;
        int r1 = r0 + 8;
        int s0 = g_tok4slot[e * CAP + r0];
        int s1 = g_tok4slot[e * CAP + r1];
        float w0 = g_wslot[e * CAP + r0];
        float w1 = g_wslot[e * CAP + r1];
        float* ob0 = (s0 >= 0) ? out + (size_t)s0 * DIM : nullptr;
        float* ob1 = (s1 >= 0) ? out + (size_t)s1 * DIM : nullptr;
#pragma unroll
        for (int nt = 0; nt < 4; nt++) {
            int col = n0 + wn * 32 + nt * 8 + cgi;
            if (ob0) {
                atomicAdd(ob0 + col,     w0 * acc[mt][nt][0]);
                atomicAdd(ob0 + col + 1, w0 * acc[mt][nt][1]);
            }
            if (ob1) {
                atomicAdd(ob1 + col,     w1 * acc[mt][nt][2]);
                atomicAdd(ob1 + col + 1, w1 * acc[mt][nt][3]);
            }
        }
    }
}

// ---------------- launch -----------------------------------------------------
extern "C" void kernel_launch(void* const* d_in, const int* in_sizes, int n_in,
                              void* d_out, int out_size) {
    (void)in_sizes; (void)n_in;
    const float* x  = (const float*)d_in[0];
    const float* wg = (const float*)d_in[1];
    const float* w1 = (const float*)d_in[2];
    const float* w3 = (const float*)d_in[3];
    const float* w2 = (const float*)d_in[4];
    float* out = (float*)d_out;

    static cudaStream_t s1 = nullptr;
    static cudaEvent_t evFork = nullptr, evW13 = nullptr, evW2 = nullptr;
    if (!s1) {
        cudaStreamCreateWithFlags(&s1, cudaStreamNonBlocking);
        cudaEventCreateWithFlags(&evFork, cudaEventDisableTiming);
        cudaEventCreateWithFlags(&evW13, cudaEventDisableTiming);
        cudaEventCreateWithFlags(&evW2, cudaEventDisableTiming);
        cudaFuncSetAttribute(k_gemm_dual, cudaFuncAttributeMaxDynamicSharedMemorySize, D_GSMEM);
        cudaFuncSetAttribute(k_gemm_s, cudaFuncAttributeMaxDynamicSharedMemorySize, S_GSMEM);
    }

    void *p_ah, *p_w1h, *p_w3h, *p_w2h, *p_hh;
    cudaGetSymbolAddress(&p_ah, g_ah);
    cudaGetSymbolAddress(&p_w1h, g_w1h); cudaGetSymbolAddress(&p_w3h, g_w3h);
    cudaGetSymbolAddress(&p_w2h, g_w2h);
    cudaGetSymbolAddress(&p_hh, g_hh);

    const size_t NW4 = (size_t)NE * DIM * FF / 4;
    int wgrid = (int)((NW4 + 255) / 256);

    cudaEventRecord(evFork, 0);
    cudaStreamWaitEvent(s1, evFork, 0);

    // side stream: w1+w3 conversion FIRST (full bandwidth, critical path),
    // then w2 conversion (hidden under compute-bound gemm_dual).
    k_wcvt2<<<wgrid, 256, 0, s1>>>((const float4*)w1, (uint2*)p_w1h,
                                   (const float4*)w3, (uint2*)p_w3h, NW4);
    cudaEventRecord(evW13, s1);
    k_wcvt<<<wgrid, 256, 0, s1>>>((const float4*)w2, (uint2*)p_w2h, NW4);
    cudaEventRecord(evW2, s1);

    // main stream: zero out (CE) + gating + dispatch (overlaps conversions)
    cudaMemsetAsync(out, 0, (size_t)out_size * sizeof(float), 0);
    k_prep<<<(NE * CAP + 255) / 256, 256>>>();
    k_logits<<<S_TOK, 128>>>(x, wg);
    k_top2<<<S_TOK / 256, 256>>>();
    k_scan<<<1, 256>>>(out, out_size);
    k_dispatch_h<<<NE * CAP, 256>>>(x);

    cudaStreamWaitEvent(0, evW13, 0);
    dim3 grid1(FF / 64, CAP / 128, NE);    // (86, 8, 8)
    k_gemm_dual<<<grid1, 256, D_GSMEM>>>((const fp16*)p_ah, (const fp16*)p_w1h,
                                         (const fp16*)p_w3h, (fp16*)p_hh,
                                         FF, DIM);
    cudaStreamWaitEvent(0, evW2, 0);
    dim3 grid2(DIM / 128, CAP / 128, NE);  // (16, 8, 8)
    k_gemm_s<<<grid2, 256, S_GSMEM>>>((const fp16*)p_hh, (const fp16*)p_w2h,
                                      out, DIM, FF);
}

// round 16
// speedup vs baseline: 1.0104x; 1.0104x over previous
#include <cuda_runtime.h>
#include <cuda_fp16.h>
#include <cstdint>

#define S_TOK 4096
#define DIM   2048
#define NE    8
#define FF    5504
#define CAP   1024

typedef __half fp16;

// ---------------- device-global scratch ------------------------------------
__device__ float g_logits[S_TOK * NE];
__device__ int   g_idx1[S_TOK], g_idx2[S_TOK];
__device__ float g_g1[S_TOK], g_g2[S_TOK];
__device__ int   g_slot1[S_TOK], g_slot2[S_TOK];
__device__ int   g_tok4slot[NE * CAP];
__device__ float g_wslot[NE * CAP];
__device__ int   g_count1[NE];
__device__ float g_me[NE];
__device__ float g_laux;

__device__ fp16  g_ah[(size_t)NE * CAP * DIM];
__device__ fp16  g_w1h[(size_t)NE * DIM * FF];
__device__ fp16  g_w3h[(size_t)NE * DIM * FF];
__device__ fp16  g_w2h[(size_t)NE * FF * DIM];
__device__ fp16  g_hh[(size_t)NE * CAP * FF];

// ---------------- helpers ----------------------------------------------------
__device__ __forceinline__ uint32_t smem_to_u32(const void* p) {
    uint32_t a;
    asm("{ .reg .u64 t; cvta.to.shared.u64 t, %1; cvt.u32.u64 %0, t; }"
        : "=r"(a) : "l"(p));
    return a;
}
__device__ __forceinline__ void cpasync16(uint32_t dst, const void* src) {
    asm volatile("cp.async.cg.shared.global [%0], [%1], 16;" :: "r"(dst), "l"(src));
}
#define CP_COMMIT() asm volatile("cp.async.commit_group;" ::: "memory")
#define CP_WAIT1()  asm volatile("cp.async.wait_group 1;" ::: "memory")
#define CP_WAIT0()  asm volatile("cp.async.wait_group 0;" ::: "memory")

__device__ __forceinline__ void ldsm_x4(uint32_t& r0, uint32_t& r1, uint32_t& r2,
                                        uint32_t& r3, uint32_t a) {
    asm volatile("ldmatrix.sync.aligned.m8n8.x4.shared.b16 {%0,%1,%2,%3}, [%4];"
                 : "=r"(r0), "=r"(r1), "=r"(r2), "=r"(r3) : "r"(a));
}
__device__ __forceinline__ void ldsm_x4t(uint32_t& r0, uint32_t& r1, uint32_t& r2,
                                         uint32_t& r3, uint32_t a) {
    asm volatile("ldmatrix.sync.aligned.m8n8.x4.trans.shared.b16 {%0,%1,%2,%3}, [%4];"
                 : "=r"(r0), "=r"(r1), "=r"(r2), "=r"(r3) : "r"(a));
}
__device__ __forceinline__ void mma16816(float* c, const uint32_t* a,
                                         uint32_t b0, uint32_t b1) {
    asm volatile("mma.sync.aligned.m16n8k16.row.col.f32.f16.f16.f32 "
                 "{%0,%1,%2,%3},{%4,%5,%6,%7},{%8,%9},{%0,%1,%2,%3};"
                 : "+f"(c[0]), "+f"(c[1]), "+f"(c[2]), "+f"(c[3])
                 : "r"(a[0]), "r"(a[1]), "r"(a[2]), "r"(a[3]), "r"(b0), "r"(b1));
}
__device__ __forceinline__ uint32_t pkh(fp16 a, fp16 b) {
    return (uint32_t)__half_as_ushort(a) | ((uint32_t)__half_as_ushort(b) << 16);
}

// ---------------- prep: reset small scratch only -----------------------------
__global__ void k_prep() {
    int i = blockIdx.x * blockDim.x + threadIdx.x;
    if (i < NE * CAP) g_tok4slot[i] = -1;
    if (i < NE) g_me[i] = 0.f;
}

// ---------------- gating ------------------------------------------------------
__global__ void k_logits(const float* __restrict__ x, const float* __restrict__ wg) {
    int s = blockIdx.x;
    float acc[NE];
#pragma unroll
    for (int e = 0; e < NE; e++) acc[e] = 0.f;
    const float* xr = x + (size_t)s * DIM;
    for (int j = threadIdx.x; j < DIM; j += blockDim.x) {
        float xv = xr[j];
        float4 w0 = *(const float4*)(wg + (size_t)j * NE);
        float4 w1v = *(const float4*)(wg + (size_t)j * NE + 4);
        acc[0] += xv * w0.x;  acc[1] += xv * w0.y;
        acc[2] += xv * w0.z;  acc[3] += xv * w0.w;
        acc[4] += xv * w1v.x; acc[5] += xv * w1v.y;
        acc[6] += xv * w1v.z; acc[7] += xv * w1v.w;
    }
#pragma unroll
    for (int off = 16; off; off >>= 1)
#pragma unroll
        for (int e = 0; e < NE; e++)
            acc[e] += __shfl_down_sync(0xffffffffu, acc[e], off);
    __shared__ float red[4][NE];
    int lane = threadIdx.x & 31, wp = threadIdx.x >> 5;
    if (lane == 0)
#pragma unroll
        for (int e = 0; e < NE; e++) red[wp][e] = acc[e];
    __syncthreads();
    if (threadIdx.x < NE)
        g_logits[(size_t)s * NE + threadIdx.x] =
            red[0][threadIdx.x] + red[1][threadIdx.x] +
            red[2][threadIdx.x] + red[3][threadIdx.x];
}
__global__ void k_top2() {
    __shared__ float sme[NE];
    if (threadIdx.x < NE) sme[threadIdx.x] = 0.f;
    __syncthreads();
    int s = blockIdx.x * blockDim.x + threadIdx.x;
    float l[NE];
    float4 a = *(const float4*)(g_logits + (size_t)s * NE);
    float4 b = *(const float4*)(g_logits + (size_t)s * NE + 4);
    l[0]=a.x; l[1]=a.y; l[2]=a.z; l[3]=a.w; l[4]=b.x; l[5]=b.y; l[6]=b.z; l[7]=b.w;
    float mx = l[0];
#pragma unroll
    for (int e = 1; e < NE; e++) mx = fmaxf(mx, l[e]);
    float g[NE], sum = 0.f;
#pragma unroll
    for (int e = 0; e < NE; e++) { g[e] = __expf(l[e] - mx); sum += g[e]; }
    float inv = 1.f / sum;
    int i1 = 0; float b1 = l[0];
#pragma unroll
    for (int e = 1; e < NE; e++) if (l[e] > b1) { b1 = l[e]; i1 = e; }
    int i2 = 0; float b2 = -3.0e38f;
#pragma unroll
    for (int e = 0; e < NE; e++) if (e != i1 && l[e] > b2) { b2 = l[e]; i2 = e; }
    g_idx1[s] = i1; g_idx2[s] = i2;
    g_g1[s] = g[i1] * inv; g_g2[s] = g[i2] * inv;
#pragma unroll
    for (int e = 0; e < NE; e++) atomicAdd(&sme[e], g[e] * inv);
    __syncthreads();
    if (threadIdx.x < NE) atomicAdd(&g_me[threadIdx.x], sme[threadIdx.x]);
}
// scan + per-slot gate weights + aux outputs (single block)
__global__ void k_scan(float* __restrict__ out, int out_size) {
    __shared__ int si1[S_TOK], si2[S_TOK];
    int tid = threadIdx.x;
    for (int i = tid; i < S_TOK; i += blockDim.x) { si1[i] = g_idx1[i]; si2[i] = g_idx2[i]; }
    __syncthreads();
    int lane = tid & 31, e = tid >> 5;
    unsigned lm = (1u << lane) - 1u;
    if (e < NE) {
        int c1 = 0;
        for (int s0 = 0; s0 < S_TOK; s0 += 32) {
            int s = s0 + lane;
            int m = (si1[s] == e);
            unsigned bal = __ballot_sync(0xffffffffu, m);
            if (m) {
                int pos = c1 + __popc(bal & lm);
                if (pos < CAP) { g_slot1[s] = pos; g_tok4slot[e * CAP + pos] = s; }
                else g_slot1[s] = -1;
            }
            c1 += __popc(bal);
        }
        if (lane == 0) g_count1[e] = c1;
        int c2 = c1;
        for (int s0 = 0; s0 < S_TOK; s0 += 32) {
            int s = s0 + lane;
            int m = (si2[s] == e);
            unsigned bal = __ballot_sync(0xffffffffu, m);
            if (m) {
                int pos = c2 + __popc(bal & lm);
                if (pos < CAP) { g_slot2[s] = pos; g_tok4slot[e * CAP + pos] = s; }
                else g_slot2[s] = -1;
            }
            c2 += __popc(bal);
        }
    }
    __syncthreads();
    for (int s = tid; s < S_TOK; s += blockDim.x) {
        int sl1 = g_slot1[s], sl2 = g_slot2[s];
        float g1 = (sl1 >= 0) ? g_g1[s] : 0.f;
        float g2 = (sl2 >= 0) ? g_g2[s] : 0.f;
        float dn = fmaxf(g1 + g2, 1e-9f);
        if (sl1 >= 0) g_wslot[g_idx1[s] * CAP + sl1] = g1 / dn;
        if (sl2 >= 0) g_wslot[g_idx2[s] * CAP + sl2] = g2 / dn;
    }
    if (tid == 0) {
        float acc = 0.f;
        for (int i = 0; i < NE; i++)
            acc += (g_me[i] / (float)S_TOK) * ((float)g_count1[i] / (float)S_TOK);
        g_laux = acc * (float)NE;
        size_t base = (size_t)S_TOK * DIM;
        if ((size_t)out_size > base) out[base] = g_laux;
    }
    if (tid >= 1 && tid <= NE) {
        size_t base = (size_t)S_TOK * DIM;
        if ((size_t)out_size >= base + 1 + NE)
            out[base + tid] = (float)g_count1[tid - 1];
    }
}

// ---------------- dispatch: gather token rows -> A fp16 ---------------------
__global__ void k_dispatch_h(const float* __restrict__ x) {
    int slot = blockIdx.x;
    int s = g_tok4slot[slot];
    uint2* ah = (uint2*)(g_ah + (size_t)slot * DIM);
    if (s >= 0) {
        const float4* xr = (const float4*)(x + (size_t)s * DIM);
        for (int j = threadIdx.x; j < DIM / 4; j += blockDim.x) {
            float4 v = xr[j];
            ah[j] = make_uint2(pkh(__float2half_rn(v.x), __float2half_rn(v.y)),
                               pkh(__float2half_rn(v.z), __float2half_rn(v.w)));
        }
    } else {
        uint2 z = make_uint2(0u, 0u);
        for (int j = threadIdx.x; j < DIM / 4; j += blockDim.x) ah[j] = z;
    }
}

// ---------------- fused dual-source weight conversion (w1 + w3) -------------
__global__ void k_wcvt2(const float4* __restrict__ s1, uint2* __restrict__ d1,
                        const float4* __restrict__ s2, uint2* __restrict__ d2,
                        size_t n4) {
    size_t i = (size_t)blockIdx.x * blockDim.x + threadIdx.x;
    if (i >= n4) return;
    float4 a = s1[i];
    d1[i] = make_uint2(pkh(__float2half_rn(a.x), __float2half_rn(a.y)),
                       pkh(__float2half_rn(a.z), __float2half_rn(a.w)));
    float4 b = s2[i];
    d2[i] = make_uint2(pkh(__float2half_rn(b.x), __float2half_rn(b.y)),
                       pkh(__float2half_rn(b.z), __float2half_rn(b.w)));
}

// ---------------- tiling constants (BK=64) ----------------------------------
#define ASTR64  144u
#define A_SZ64  (128u * ASTR64)           // 18432
#define BSTRN   272u
#define BSTRH   144u
#define NSTAGE  3

// ---------------- dual-B SwiGLU GEMM + embedded w2 conversion ---------------
// 256 thr, BM=128 BN=64 BK=64; each of the 5504 CTAs also converts 4096
// float4s (1/5504) of w2 fp32->fp16 after its epilogue (rides spare HBM bw).
#define D_BSZ   (64u * BSTRH)
#define D_STG   (A_SZ64 + 2u * D_BSZ)
#define D_GSMEM (NSTAGE * D_STG)

__global__ void __launch_bounds__(256, 2)
k_gemm_dual(const fp16* __restrict__ Ag, const fp16* __restrict__ B1g,
            const fp16* __restrict__ B3g, fp16* __restrict__ Hg,
            const float4* __restrict__ W2src, uint2* __restrict__ W2dst,
            int N, int K) {
    extern __shared__ __align__(16) uint8_t smem[];
    const int M = CAP;
    int tid = threadIdx.x, lane = tid & 31, wid = tid >> 5;
    int wm = wid & 1, wn = wid >> 1;
    int n0 = blockIdx.x * 64, m0 = blockIdx.y * 128, e = blockIdx.z;
    const fp16* A0 = Ag + (size_t)e * M * K;
    const fp16* B1 = B1g + (size_t)e * K * N;
    const fp16* B3 = B3g + (size_t)e * K * N;
    const int NIT = K / 64;
    uint32_t sb = smem_to_u32(smem);

    float acc1[4][2][4], acc3[4][2][4];
#pragma unroll
    for (int a = 0; a < 4; a++)
#pragma unroll
        for (int b = 0; b < 2; b++)
#pragma unroll
            for (int c = 0; c < 4; c++) { acc1[a][b][c] = 0.f; acc3[a][b][c] = 0.f; }

    auto load_stage = [&](int kc, int slot) {
        uint32_t st = sb + (uint32_t)slot * D_STG;
#pragma unroll
        for (int j = 0; j < 4; j++) {
            int id = tid + j * 256;
            int row = id >> 3, c = id & 7;
            cpasync16(st + (uint32_t)row * ASTR64 + c * 16,
                      A0 + (size_t)(m0 + row) * K + kc * 64 + c * 8);
        }
#pragma unroll
        for (int j = 0; j < 2; j++) {
            int id = tid + j * 256;
            int k = id >> 3, c = id & 7;
            const size_t gb = (size_t)(kc * 64 + k) * N + n0 + c * 8;
            cpasync16(st + A_SZ64 + (uint32_t)k * BSTRH + c * 16, B1 + gb);
            cpasync16(st + A_SZ64 + D_BSZ + (uint32_t)k * BSTRH + c * 16, B3 + gb);
        }
    };

    int mm = lane >> 3;
    int rowin = (mm & 1) * 8 + (lane & 7);
    int c0 = mm >> 1;
    uint32_t aOff = (uint32_t)(wm * 64 + rowin) * ASTR64 + (uint32_t)c0 * 16;
    int p = lane >> 4, mrow = (lane >> 3) & 1;
    int kin = mrow * 8 + (lane & 7);
    uint32_t bOff = (uint32_t)kin * BSTRH + (uint32_t)(wn * 2 + p) * 16;

    load_stage(0, 0); CP_COMMIT();
    load_stage(1, 1); CP_COMMIT();
    for (int i = 0; i < NIT; i++) {
        if (i + 1 < NIT) CP_WAIT1(); else CP_WAIT0();
        __syncthreads();
        uint32_t st = sb + (uint32_t)(i % NSTAGE) * D_STG;
#pragma unroll
        for (int s = 0; s < 4; s++) {
            uint32_t a[4][4], b1r[4], b3r[4];
#pragma unroll
            for (int mt = 0; mt < 4; mt++)
                ldsm_x4(a[mt][0], a[mt][1], a[mt][2], a[mt][3],
                        st + aOff + (uint32_t)mt * (16u * ASTR64) + (uint32_t)s * 32);
            ldsm_x4t(b1r[0], b1r[1], b1r[2], b1r[3],
                     st + A_SZ64 + bOff + (uint32_t)s * (16u * BSTRH));
            ldsm_x4t(b3r[0], b3r[1], b3r[2], b3r[3],
                     st + A_SZ64 + D_BSZ + bOff + (uint32_t)s * (16u * BSTRH));
#pragma unroll
            for (int mt = 0; mt < 4; mt++)
#pragma unroll
                for (int nt = 0; nt < 2; nt++) {
                    mma16816(acc1[mt][nt], a[mt], b1r[nt * 2], b1r[nt * 2 + 1]);
                    mma16816(acc3[mt][nt], a[mt], b3r[nt * 2], b3r[nt * 2 + 1]);
                }
        }
        if (i + 2 < NIT) load_stage(i + 2, (i + 2) % NSTAGE);
        CP_COMMIT();
    }

    int rg = lane >> 2, cgi = (lane & 3) * 2;
    size_t ebase = (size_t)e * M * N;
#pragma unroll
    for (int mt = 0; mt < 4; mt++)
#pragma unroll
        for (int nt = 0; nt < 2; nt++) {
            int row = m0 + wm * 64 + mt * 16 + rg;
            int col = n0 + wn * 16 + nt * 8 + cgi;
            size_t o0 = ebase + (size_t)row * N + col;
            size_t o1 = ebase + (size_t)(row + 8) * N + col;
            float t0 = acc1[mt][nt][0], t1 = acc1[mt][nt][1];
            float t2 = acc1[mt][nt][2], t3 = acc1[mt][nt][3];
            float h0 = t0 / (1.f + __expf(-t0)) * acc3[mt][nt][0];
            float h1 = t1 / (1.f + __expf(-t1)) * acc3[mt][nt][1];
            float h2 = t2 / (1.f + __expf(-t2)) * acc3[mt][nt][2];
            float h3 = t3 / (1.f + __expf(-t3)) * acc3[mt][nt][3];
            *(uint32_t*)(Hg + o0) = pkh(__float2half_rn(h0), __float2half_rn(h1));
            *(uint32_t*)(Hg + o1) = pkh(__float2half_rn(h2), __float2half_rn(h3));
        }

    // embedded w2 conversion: this CTA's 4096-float4 slice (coalesced)
    {
        size_t cta = (size_t)blockIdx.x +
                     (size_t)gridDim.x * (blockIdx.y + (size_t)gridDim.y * blockIdx.z);
        size_t base = cta * 4096 + tid;
#pragma unroll
        for (int j = 0; j < 16; j++) {
            size_t idx = base + (size_t)j * 256;
            float4 v = W2src[idx];
            W2dst[idx] = make_uint2(pkh(__float2half_rn(v.x), __float2half_rn(v.y)),
                                    pkh(__float2half_rn(v.z), __float2half_rn(v.w)));
        }
    }
}

// ---------------- single-B GEMM + fused combine epilogue (R12 proven) -------
#define S_BSZ   (64u * BSTRN)
#define S_STG   (A_SZ64 + S_BSZ)
#define S_GSMEM (NSTAGE * S_STG)

__global__ void __launch_bounds__(256, 2)
k_gemm_s(const fp16* __restrict__ Ag, const fp16* __restrict__ Bg,
         float* __restrict__ out, int N, int K) {
    extern __shared__ __align__(16) uint8_t smem[];
    const int M = CAP;
    int tid = threadIdx.x, lane = tid & 31, wid = tid >> 5;
    int wm = wid & 1, wn = wid >> 1;
    int n0 = blockIdx.x * 128, m0 = blockIdx.y * 128, e = blockIdx.z;
    const fp16* A0 = Ag + (size_t)e * M * K;
    const fp16* B0 = Bg + (size_t)e * K * N;
    const int NIT = K / 64;
    uint32_t sb = smem_to_u32(smem);

    float acc[4][4][4];
#pragma unroll
    for (int a = 0; a < 4; a++)
#pragma unroll
        for (int b = 0; b < 4; b++)
#pragma unroll
            for (int c = 0; c < 4; c++) acc[a][b][c] = 0.f;

    auto load_stage = [&](int kc, int slot) {
        uint32_t st = sb + (uint32_t)slot * S_STG;
#pragma unroll
        for (int j = 0; j < 4; j++) {
            int id = tid + j * 256;
            int row = id >> 3, c = id & 7;
            cpasync16(st + (uint32_t)row * ASTR64 + c * 16,
                      A0 + (size_t)(m0 + row) * K + kc * 64 + c * 8);
        }
#pragma unroll
        for (int j = 0; j < 4; j++) {
            int id = tid + j * 256;
            int k = id >> 4, c = id & 15;
            cpasync16(st + A_SZ64 + (uint32_t)k * BSTRN + c * 16,
                      B0 + (size_t)(kc * 64 + k) * N + n0 + c * 8);
        }
    };

    int mm = lane >> 3;
    int rowin = (mm & 1) * 8 + (lane & 7);
    int c0 = mm >> 1;
    uint32_t aOff = (uint32_t)(wm * 64 + rowin) * ASTR64 + (uint32_t)c0 * 16;
    int p = lane >> 4, mrow = (lane >> 3) & 1;
    int kin = mrow * 8 + (lane & 7);
    uint32_t bOff = (uint32_t)kin * BSTRN + (uint32_t)(wn * 4 + p) * 16;

    load_stage(0, 0); CP_COMMIT();
    load_stage(1, 1); CP_COMMIT();
    for (int i = 0; i < NIT; i++) {
        if (i + 1 < NIT) CP_WAIT1(); else CP_WAIT0();
        __syncthreads();
        uint32_t st = sb + (uint32_t)(i % NSTAGE) * S_STG;
#pragma unroll
        for (int s = 0; s < 4; s++) {
            uint32_t a[4][4], bh[2][4];
#pragma unroll
            for (int mt = 0; mt < 4; mt++)
                ldsm_x4(a[mt][0], a[mt][1], a[mt][2], a[mt][3],
                        st + aOff + (uint32_t)mt * (16u * ASTR64) + (uint32_t)s * 32);
            ldsm_x4t(bh[0][0], bh[0][1], bh[0][2], bh[0][3],
                     st + A_SZ64 + bOff + (uint32_t)s * (16u * BSTRN));
            ldsm_x4t(bh[1][0], bh[1][1], bh[1][2], bh[1][3],
                     st + A_SZ64 + bOff + (uint32_t)s * (16u * BSTRN) + 32u);
#pragma unroll
            for (int mt = 0; mt < 4; mt++)
#pragma unroll
                for (int nt = 0; nt < 4; nt++)
                    mma16816(acc[mt][nt], a[mt], bh[nt >> 1][(nt & 1) * 2],
                             bh[nt >> 1][(nt & 1) * 2 + 1]);
        }
        if (i + 2 < NIT) load_stage(i + 2, (i + 2) % NSTAGE);
        CP_COMMIT();
    }

    int rg = lane >> 2, cgi = (lane & 3) * 2;
#pragma unroll
    for (int mt = 0; mt < 4; mt++) {
        int r0 = m0 + wm * 64 + mt * 16 + rg;
        int r1 = r0 + 8;
        int s0 = g_tok4slot[e * CAP + r0];
        int s1 = g_tok4slot[e * CAP + r1];
        float w0 = g_wslot[e * CAP + r0];
        float w1 = g_wslot[e * CAP + r1];
        float* ob0 = (s0 >= 0) ? out + (size_t)s0 * DIM : nullptr;
        float* ob1 = (s1 >= 0) ? out + (size_t)s1 * DIM : nullptr;
#pragma unroll
        for (int nt = 0; nt < 4; nt++) {
            int col = n0 + wn * 32 + nt * 8 + cgi;
            if (ob0) {
                atomicAdd(ob0 + col,     w0 * acc[mt][nt][0]);
                atomicAdd(ob0 + col + 1, w0 * acc[mt][nt][1]);
            }
            if (ob1) {
                atomicAdd(ob1 + col,     w1 * acc[mt][nt][2]);
                atomicAdd(ob1 + col + 1, w1 * acc[mt][nt][3]);
            }
        }
    }
}

// ---------------- launch -----------------------------------------------------
extern "C" void kernel_launch(void* const* d_in, const int* in_sizes, int n_in,
                              void* d_out, int out_size) {
    (void)in_sizes; (void)n_in;
    const float* x  = (const float*)d_in[0];
    const float* wg = (const float*)d_in[1];
    const float* w1 = (const float*)d_in[2];
    const float* w3 = (const float*)d_in[3];
    const float* w2 = (const float*)d_in[4];
    float* out = (float*)d_out;

    static cudaStream_t s1 = nullptr;
    static cudaEvent_t evFork = nullptr, evW13 = nullptr;
    if (!s1) {
        cudaStreamCreateWithFlags(&s1, cudaStreamNonBlocking);
        cudaEventCreateWithFlags(&evFork, cudaEventDisableTiming);
        cudaEventCreateWithFlags(&evW13, cudaEventDisableTiming);
        cudaFuncSetAttribute(k_gemm_dual, cudaFuncAttributeMaxDynamicSharedMemorySize, D_GSMEM);
        cudaFuncSetAttribute(k_gemm_s, cudaFuncAttributeMaxDynamicSharedMemorySize, S_GSMEM);
    }

    void *p_ah, *p_w1h, *p_w3h, *p_w2h, *p_hh;
    cudaGetSymbolAddress(&p_ah, g_ah);
    cudaGetSymbolAddress(&p_w1h, g_w1h); cudaGetSymbolAddress(&p_w3h, g_w3h);
    cudaGetSymbolAddress(&p_w2h, g_w2h);
    cudaGetSymbolAddress(&p_hh, g_hh);

    const size_t NW4 = (size_t)NE * DIM * FF / 4;
    int wgrid = (int)((NW4 + 255) / 256);

    cudaEventRecord(evFork, 0);
    cudaStreamWaitEvent(s1, evFork, 0);

    // side stream: w1+w3 conversion only (w2 is converted inside gemm_dual)
    k_wcvt2<<<wgrid, 256, 0, s1>>>((const float4*)w1, (uint2*)p_w1h,
                                   (const float4*)w3, (uint2*)p_w3h, NW4);
    cudaEventRecord(evW13, s1);

    // main stream: zero out (CE) + gating + dispatch (overlaps conversions)
    cudaMemsetAsync(out, 0, (size_t)out_size * sizeof(float), 0);
    k_prep<<<(NE * CAP + 255) / 256, 256>>>();
    k_logits<<<S_TOK, 128>>>(x, wg);
    k_top2<<<S_TOK / 256, 256>>>();
    k_scan<<<1, 256>>>(out, out_size);
    k_dispatch_h<<<NE * CAP, 256>>>(x);

    cudaStreamWaitEvent(0, evW13, 0);
    dim3 grid1(FF / 64, CAP / 128, NE);    // (86, 8, 8) = 5504 CTAs
    k_gemm_dual<<<grid1, 256, D_GSMEM>>>((const fp16*)p_ah, (const fp16*)p_w1h,
                                         (const fp16*)p_w3h, (fp16*)p_hh,
                                         (const float4*)w2, (uint2*)p_w2h,
                                         FF, DIM);
    // w2h complete via stream order (every gemm_dual CTA converts its slice)
    dim3 grid2(DIM / 128, CAP / 128, NE);  // (16, 8, 8)
    k_gemm_s<<<grid2, 256, S_GSMEM>>>((const fp16*)p_hh, (const fp16*)p_w2h,
                                      out, DIM, FF);
}